// round 1
// baseline (speedup 1.0000x reference)
#include <cuda_runtime.h>
#include <math.h>

// Problem constants
#define B_  4
#define C_  64
#define K_  32
#define N_  131072           // D*H*W = 32*64*64
#define TN  256              // n-tile per block
#define XS  257              // X_sh row stride (pad)
#define AS  257              // A_sh row stride (pad)
#define E_ELEMS (B_*K_*C_)   // 8192

// Scratch for per-(b,k) softmax sums (no device allocs allowed)
__device__ float g_asum[B_*K_];

// ---------------------------------------------------------------------------
// Kernel 0: zero the E region of out + the asum scratch (must run every
// launch — graph replays re-accumulate).
// ---------------------------------------------------------------------------
__global__ void enc_init(float* __restrict__ out) {
    int i = blockIdx.x * 256 + threadIdx.x;
    if (i < E_ELEMS) out[i] = 0.0f;
    if (i < B_*K_)   g_asum[i] = 0.0f;
}

// ---------------------------------------------------------------------------
// Kernel 1: fused logits + softmax + coefA store + block-local A^T X GEMM,
// flushed via float REDG into the E region.
// One block = one (b, 256-n) tile. Grid = 4 * 512 = 2048 blocks.
// ---------------------------------------------------------------------------
__global__ __launch_bounds__(256, 2) void enc_main(
    const float* __restrict__ X,    // (B, C, N)
    const float* __restrict__ cwg,  // (K, C)
    const float* __restrict__ sclg, // (K,)
    float* __restrict__ out)        // [E (B,K,C) | coefA (B,K,N)]
{
    extern __shared__ float smem[];
    float* cw  = smem;               // 2048
    float* scl = smem + 2048;        // 32
    float* c2  = smem + 2080;        // 32
    float* Xs  = smem + 2112;        // 64*XS  (X tile, [c][n], pad 257)
    float* As  = Xs + 64 * XS;       // 32*AS  (A tile, [k][n], pad 257)

    const int tid = threadIdx.x;
    const int b   = blockIdx.x >> 9;         // /512
    const int n0  = (blockIdx.x & 511) << 8; // *256

    // --- Phase 0: stage codewords, scale, X tile ---
    for (int i = tid; i < K_*C_; i += 256) cw[i] = cwg[i];
    if (tid < K_) scl[tid] = sclg[tid];

    const float* Xb = X + (size_t)b * C_ * N_ + n0;
    #pragma unroll 8
    for (int c = 0; c < C_; ++c) {
        // lanes consecutive n -> coalesced LDG, conflict-free STS
        Xs[c * XS + tid] = Xb[(size_t)c * N_ + tid];
    }
    __syncthreads();

    if (tid < K_) {
        float s = 0.f;
        #pragma unroll
        for (int c = 0; c < C_; ++c) { float v = cw[tid*C_ + c]; s += v*v; }
        c2[tid] = s;
    }
    __syncthreads();

    // --- Phase 1: per-thread n = n0 + tid: dots, softmax, store A ---
    float dots[K_];
    #pragma unroll
    for (int k = 0; k < K_; ++k) dots[k] = 0.f;
    float x2 = 0.f;

    const float4* cw4 = (const float4*)cw;   // cw rows are 64 floats, 16B aligned
    for (int c4 = 0; c4 < 16; ++c4) {
        float x0 = Xs[(c4*4+0)*XS + tid];
        float x1 = Xs[(c4*4+1)*XS + tid];
        float xa = Xs[(c4*4+2)*XS + tid];
        float xb = Xs[(c4*4+3)*XS + tid];
        x2 += x0*x0 + x1*x1 + xa*xa + xb*xb;
        #pragma unroll
        for (int k = 0; k < K_; ++k) {
            float4 w = cw4[k*16 + c4];       // broadcast LDS.128
            dots[k] += x0*w.x + x1*w.y + xa*w.z + xb*w.w;
        }
    }

    float m = -1e30f;
    #pragma unroll
    for (int k = 0; k < K_; ++k) {
        float l = scl[k] * fmaf(-2.f, dots[k], x2 + c2[k]);
        dots[k] = l;
        m = fmaxf(m, l);
    }
    float s = 0.f;
    #pragma unroll
    for (int k = 0; k < K_; ++k) { float e = __expf(dots[k] - m); dots[k] = e; s += e; }
    float inv = 1.0f / s;

    float* coefA = out + E_ELEMS + (size_t)b * K_ * N_ + n0 + tid;
    #pragma unroll
    for (int k = 0; k < K_; ++k) {
        float a = dots[k] * inv;
        coefA[(size_t)k * N_] = a;   // coalesced STG per k
        As[k * AS + tid] = a;        // conflict-free STS
    }
    __syncthreads();

    // --- Phase 2: cooperative AtX tile GEMM: 32x64 output, 8 outputs/thread
    // thread -> 4 k rows (k0..k0+3), 2 c cols (c0, c0+1)
    const int k0 = (tid & 7) * 4;
    const int cg = tid >> 3;
    const int c0 = cg * 2;
    float a00=0,a01=0,a10=0,a11=0,a20=0,a21=0,a30=0,a31=0;
    float s0=0,s1=0,s2=0,s3=0;
    const float* Ap = As + k0 * AS;
    const float* Xp = Xs + c0 * XS;

    #pragma unroll 4
    for (int n = 0; n < TN; ++n) {
        float v0 = Ap[0*AS + n];   // broadcast (4 lanes share), banks conflict-free
        float v1 = Ap[1*AS + n];
        float v2 = Ap[2*AS + n];
        float v3 = Ap[3*AS + n];
        float x0 = Xp[0*XS + n];   // broadcast (8 lanes share)
        float x1 = Xp[1*XS + n];
        a00 += v0*x0; a01 += v0*x1;
        a10 += v1*x0; a11 += v1*x1;
        a20 += v2*x0; a21 += v2*x1;
        a30 += v3*x0; a31 += v3*x1;
        if (cg == 0) { s0 += v0; s1 += v1; s2 += v2; s3 += v3; }
    }

    float* E = out + b * (K_*C_);
    atomicAdd(&E[(k0+0)*C_ + c0    ], a00);
    atomicAdd(&E[(k0+0)*C_ + c0 + 1], a01);
    atomicAdd(&E[(k0+1)*C_ + c0    ], a10);
    atomicAdd(&E[(k0+1)*C_ + c0 + 1], a11);
    atomicAdd(&E[(k0+2)*C_ + c0    ], a20);
    atomicAdd(&E[(k0+2)*C_ + c0 + 1], a21);
    atomicAdd(&E[(k0+3)*C_ + c0    ], a30);
    atomicAdd(&E[(k0+3)*C_ + c0 + 1], a31);
    if (cg == 0) {
        atomicAdd(&g_asum[b*K_ + k0 + 0], s0);
        atomicAdd(&g_asum[b*K_ + k0 + 1], s1);
        atomicAdd(&g_asum[b*K_ + k0 + 2], s2);
        atomicAdd(&g_asum[b*K_ + k0 + 3], s3);
    }
}

// ---------------------------------------------------------------------------
// Kernel 2: E[b,k,c] -= Asum[b,k] * C[k,c]
// ---------------------------------------------------------------------------
__global__ void enc_final(const float* __restrict__ cwg, float* __restrict__ out) {
    int i = blockIdx.x * 256 + threadIdx.x;
    if (i >= E_ELEMS) return;
    int c  = i & 63;
    int bk = i >> 6;          // b*32 + k
    int k  = bk & 31;
    out[i] -= g_asum[bk] * cwg[k*64 + c];
}

// ---------------------------------------------------------------------------
extern "C" void kernel_launch(void* const* d_in, const int* in_sizes, int n_in,
                              void* d_out, int out_size) {
    const float* X   = (const float*)d_in[0];
    const float* cwg = (const float*)d_in[1];
    const float* scl = (const float*)d_in[2];
    float* out = (float*)d_out;

    const int smem_bytes = (2112 + 64*XS + 32*AS) * 4;  // 107,136 B
    cudaFuncSetAttribute(enc_main, cudaFuncAttributeMaxDynamicSharedMemorySize,
                         smem_bytes);

    enc_init<<<32, 256>>>(out);
    enc_main<<<2048, 256, smem_bytes>>>(X, cwg, scl, out);
    enc_final<<<32, 256>>>(cwg, out);
}

// round 3
// speedup vs baseline: 1.3386x; 1.3386x over previous
#include <cuda_runtime.h>

#define B_  4
#define C_  64
#define K_  32
#define N_  131072           // D*H*W
#define XS  260              // X tile stride (words)
#define LS  260              // L/A tile stride (words)
#define CWS 36               // transposed codeword stride
#define E_ELEMS (B_*K_*C_)   // 8192

__device__ float g_asum[B_*K_];

typedef unsigned long long u64;

__device__ __forceinline__ u64 ffma2(u64 a, u64 b, u64 c) {
    u64 d; asm("fma.rn.f32x2 %0, %1, %2, %3;" : "=l"(d) : "l"(a), "l"(b), "l"(c));
    return d;
}
__device__ __forceinline__ u64 fadd2(u64 a, u64 b) {
    u64 d; asm("add.rn.f32x2 %0, %1, %2;" : "=l"(d) : "l"(a), "l"(b));
    return d;
}
__device__ __forceinline__ u64 pack2(float lo, float hi) {
    u64 d; asm("mov.b64 %0, {%1, %2};" : "=l"(d) : "f"(lo), "f"(hi));
    return d;
}
__device__ __forceinline__ float2 unpack2(u64 v) {
    float2 r; asm("mov.b64 {%0, %1}, %2;" : "=f"(r.x), "=f"(r.y) : "l"(v));
    return r;
}

// ---------------------------------------------------------------------------
__global__ void enc_init(float* __restrict__ out) {
    int i = blockIdx.x * 256 + threadIdx.x;
    if (i < E_ELEMS) out[i] = 0.0f;
    if (i < B_*K_)   g_asum[i] = 0.0f;
}

// ---------------------------------------------------------------------------
__global__ __launch_bounds__(256, 2) void enc_main(
    const float* __restrict__ X,    // (B, C, N)
    const float* __restrict__ cwg,  // (K, C)
    const float* __restrict__ sclg, // (K,)
    float* __restrict__ out)        // [E | coefA]
{
    extern __shared__ float sm[];
    float* Xs  = sm;                  // 64*260
    float* Lb  = Xs + 64*XS;          // 32*260  (logits, then A in place)
    float* cwt = Lb + 32*LS;          // 64*36   codewords transposed [c][k]
    float* x2s = cwt + 64*CWS;        // 256
    float* scl = x2s + 256;           // 32
    float* c4  = scl + 32;            // 32*4  (scl, -2*scl, scl*c2, 0)

    const int tid = threadIdx.x;
    const int b   = blockIdx.x >> 9;
    const int n0  = (blockIdx.x & 511) << 8;

    // ---- stage X tile (vectorized, coalesced) ----
    const float* Xb = X + (size_t)b * C_ * N_ + n0;
    #pragma unroll
    for (int i = 0; i < 16; ++i) {
        int f = i * 256 + tid;
        int c = f >> 6, q = f & 63;
        float4 v = *(const float4*)(Xb + (size_t)c * N_ + q * 4);
        *(float4*)(Xs + c * XS + q * 4) = v;
    }
    // ---- stage codewords transposed [c][k] ----
    #pragma unroll
    for (int i = 0; i < 8; ++i) {
        int f = i * 256 + tid;        // f = k*64 + c
        cwt[(f & 63) * CWS + (f >> 6)] = cwg[f];
    }
    if (tid < K_) scl[tid] = sclg[tid];
    __syncthreads();

    if (tid < K_) {
        float s = 0.f;
        #pragma unroll
        for (int c = 0; c < C_; ++c) { float w = cwt[c*CWS + tid]; s = fmaf(w, w, s); }
        float sc = scl[tid];
        float4 v; v.x = sc; v.y = -2.f * sc; v.z = sc * s; v.w = 0.f;
        *(float4*)(c4 + tid * 4) = v;
    }

    // ---- Phase 1: logits GEMM (dots only), 8n x 4k per thread, n-paired ----
    const int k0 = (tid & 7) * 4;
    const int nt = (tid >> 3) * 8;
    u64 acc[4][4];                    // [npair][k]
    u64 x2a[4];
    #pragma unroll
    for (int i = 0; i < 4; ++i) {
        x2a[i] = 0ull;
        #pragma unroll
        for (int j = 0; j < 4; ++j) acc[i][j] = 0ull;
    }

    #pragma unroll 8
    for (int c = 0; c < 64; ++c) {
        ulonglong2 xa = *(const ulonglong2*)(Xs + c * XS + nt);
        ulonglong2 xb = *(const ulonglong2*)(Xs + c * XS + nt + 4);
        float4 w = *(const float4*)(cwt + c * CWS + k0);
        u64 w0 = pack2(w.x, w.x), w1 = pack2(w.y, w.y);
        u64 w2 = pack2(w.z, w.z), w3 = pack2(w.w, w.w);
        acc[0][0] = ffma2(xa.x, w0, acc[0][0]);
        acc[0][1] = ffma2(xa.x, w1, acc[0][1]);
        acc[0][2] = ffma2(xa.x, w2, acc[0][2]);
        acc[0][3] = ffma2(xa.x, w3, acc[0][3]);
        acc[1][0] = ffma2(xa.y, w0, acc[1][0]);
        acc[1][1] = ffma2(xa.y, w1, acc[1][1]);
        acc[1][2] = ffma2(xa.y, w2, acc[1][2]);
        acc[1][3] = ffma2(xa.y, w3, acc[1][3]);
        acc[2][0] = ffma2(xb.x, w0, acc[2][0]);
        acc[2][1] = ffma2(xb.x, w1, acc[2][1]);
        acc[2][2] = ffma2(xb.x, w2, acc[2][2]);
        acc[2][3] = ffma2(xb.x, w3, acc[2][3]);
        acc[3][0] = ffma2(xb.y, w0, acc[3][0]);
        acc[3][1] = ffma2(xb.y, w1, acc[3][1]);
        acc[3][2] = ffma2(xb.y, w2, acc[3][2]);
        acc[3][3] = ffma2(xb.y, w3, acc[3][3]);
        x2a[0] = ffma2(xa.x, xa.x, x2a[0]);
        x2a[1] = ffma2(xa.y, xa.y, x2a[1]);
        x2a[2] = ffma2(xb.x, xb.x, x2a[2]);
        x2a[3] = ffma2(xb.y, xb.y, x2a[3]);
    }
    #pragma unroll
    for (int j = 0; j < 4; ++j)
        #pragma unroll
        for (int i = 0; i < 4; ++i)
            *(u64*)(Lb + (k0 + j) * LS + nt + 2*i) = acc[i][j];
    if ((tid & 7) == 0) {
        #pragma unroll
        for (int i = 0; i < 4; ++i) *(u64*)(x2s + nt + 2*i) = x2a[i];
    }
    __syncthreads();

    // ---- Softmax per n = tid, write coefA + A (in place over Lb) ----
    {
        float x2 = x2s[tid];
        float lg[K_];
        float mx = -1e30f;
        #pragma unroll
        for (int k = 0; k < K_; ++k) {
            float4 cc = *(const float4*)(c4 + k * 4);
            float d = Lb[k * LS + tid];
            float l = fmaf(cc.y, d, fmaf(cc.x, x2, cc.z));
            lg[k] = l;
            mx = fmaxf(mx, l);
        }
        float s = 0.f;
        #pragma unroll
        for (int k = 0; k < K_; ++k) { float e = __expf(lg[k] - mx); lg[k] = e; s += e; }
        float inv = __fdividef(1.f, s);
        float* coefA = out + E_ELEMS + (size_t)b * K_ * N_ + n0 + tid;
        #pragma unroll
        for (int k = 0; k < K_; ++k) {
            float a = lg[k] * inv;
            coefA[(size_t)k * N_] = a;     // coalesced per k
            Lb[k * LS + tid] = a;          // same words this thread read -> safe
        }
    }
    __syncthreads();

    // ---- Phase 2: E-tile GEMM A^T X, warp owns 4 k rows (broadcast A loads),
    //      lane owns columns c=lane and c=lane+32; accumulate n-paired. ----
    {
        const int wp   = tid >> 5;          // 0..7 -> k rows 4wp..4wp+3
        const int lane = tid & 31;
        const float* Ar  = Lb + (4 * wp) * LS;
        const float* Xc0 = Xs + lane * XS;
        const float* Xc1 = Xs + (lane + 32) * XS;
        u64 e00=0,e01=0,e10=0,e11=0,e20=0,e21=0,e30=0,e31=0;
        u64 s0a=0, s1a=0, s2a=0, s3a=0;

        #pragma unroll 4
        for (int n = 0; n < 256; n += 4) {
            ulonglong2 a0 = *(const ulonglong2*)(Ar + 0*LS + n);
            ulonglong2 a1 = *(const ulonglong2*)(Ar + 1*LS + n);
            ulonglong2 a2 = *(const ulonglong2*)(Ar + 2*LS + n);
            ulonglong2 a3 = *(const ulonglong2*)(Ar + 3*LS + n);
            ulonglong2 x0 = *(const ulonglong2*)(Xc0 + n);
            ulonglong2 x1 = *(const ulonglong2*)(Xc1 + n);
            e00 = ffma2(a0.x, x0.x, e00); e00 = ffma2(a0.y, x0.y, e00);
            e01 = ffma2(a0.x, x1.x, e01); e01 = ffma2(a0.y, x1.y, e01);
            e10 = ffma2(a1.x, x0.x, e10); e10 = ffma2(a1.y, x0.y, e10);
            e11 = ffma2(a1.x, x1.x, e11); e11 = ffma2(a1.y, x1.y, e11);
            e20 = ffma2(a2.x, x0.x, e20); e20 = ffma2(a2.y, x0.y, e20);
            e21 = ffma2(a2.x, x1.x, e21); e21 = ffma2(a2.y, x1.y, e21);
            e30 = ffma2(a3.x, x0.x, e30); e30 = ffma2(a3.y, x0.y, e30);
            e31 = ffma2(a3.x, x1.x, e31); e31 = ffma2(a3.y, x1.y, e31);
            s0a = fadd2(s0a, fadd2(a0.x, a0.y));
            s1a = fadd2(s1a, fadd2(a1.x, a1.y));
            s2a = fadd2(s2a, fadd2(a2.x, a2.y));
            s3a = fadd2(s3a, fadd2(a3.x, a3.y));
        }

        float* E = out + b * (K_ * C_);
        float2 f;
        f = unpack2(e00); atomicAdd(&E[(4*wp+0)*C_ + lane     ], f.x + f.y);
        f = unpack2(e01); atomicAdd(&E[(4*wp+0)*C_ + lane + 32], f.x + f.y);
        f = unpack2(e10); atomicAdd(&E[(4*wp+1)*C_ + lane     ], f.x + f.y);
        f = unpack2(e11); atomicAdd(&E[(4*wp+1)*C_ + lane + 32], f.x + f.y);
        f = unpack2(e20); atomicAdd(&E[(4*wp+2)*C_ + lane     ], f.x + f.y);
        f = unpack2(e21); atomicAdd(&E[(4*wp+2)*C_ + lane + 32], f.x + f.y);
        f = unpack2(e30); atomicAdd(&E[(4*wp+3)*C_ + lane     ], f.x + f.y);
        f = unpack2(e31); atomicAdd(&E[(4*wp+3)*C_ + lane + 32], f.x + f.y);
        if (lane == 0) {
            f = unpack2(s0a); atomicAdd(&g_asum[b*K_ + 4*wp + 0], f.x + f.y);
            f = unpack2(s1a); atomicAdd(&g_asum[b*K_ + 4*wp + 1], f.x + f.y);
            f = unpack2(s2a); atomicAdd(&g_asum[b*K_ + 4*wp + 2], f.x + f.y);
            f = unpack2(s3a); atomicAdd(&g_asum[b*K_ + 4*wp + 3], f.x + f.y);
        }
    }
}

// ---------------------------------------------------------------------------
__global__ void enc_final(const float* __restrict__ cwg, float* __restrict__ out) {
    int i = blockIdx.x * 256 + threadIdx.x;
    if (i >= E_ELEMS) return;
    int c  = i & 63;
    int bk = i >> 6;
    int k  = bk & 31;
    out[i] -= g_asum[bk] * cwg[k*64 + c];
}

// ---------------------------------------------------------------------------
extern "C" void kernel_launch(void* const* d_in, const int* in_sizes, int n_in,
                              void* d_out, int out_size) {
    const float* X   = (const float*)d_in[0];
    const float* cwg = (const float*)d_in[1];
    const float* scl = (const float*)d_in[2];
    float* out = (float*)d_out;

    const int smem_bytes = (64*XS + 32*LS + 64*CWS + 256 + 32 + 128) * 4; // 110,592 B
    cudaFuncSetAttribute(enc_main, cudaFuncAttributeMaxDynamicSharedMemorySize,
                         smem_bytes);

    enc_init<<<32, 256>>>(out);
    enc_main<<<2048, 256, smem_bytes>>>(X, cwg, scl, out);
    enc_final<<<32, 256>>>(cwg, out);
}